// round 5
// baseline (speedup 1.0000x reference)
#include <cuda_runtime.h>
#include <cuda_bf16.h>
#include <stdint.h>

// Problem constants
#define BV 2
#define TV 1536
#define DV 1024
#define HH 16
#define HD 64
#define SS 3072            // B*T
#define D3 3072            // 3*D

// Scratch (device globals: allocation-free per harness rules)
__device__ __nv_bfloat16 g_qkv_h[(size_t)SS * D3];  // 18.9 MB hi plane
__device__ __nv_bfloat16 g_qkv_l[(size_t)SS * D3];  // 18.9 MB lo plane
__device__ float g_y[(size_t)SS * DV];              // 12.6 MB

#define KC  32             // gemm k-chunk (bf16 elems)
#define ST  40             // gemm smem row stride in halves
#define ST2 80             // ... bytes
#define FST  72            // flash smem row stride in halves (64 + 8 pad)
#define FST2 144           // ... bytes

// ---------------------------------------------------------------------------
__device__ __forceinline__ uint32_t smem_u32(const void* p) {
    uint32_t a;
    asm("{ .reg .u64 t; cvta.to.shared.u64 t, %1; cvt.u32.u64 %0, t; }"
        : "=r"(a) : "l"(p));
    return a;
}
__device__ __forceinline__ void ldsm4(uint32_t r[4], uint32_t addr) {
    asm volatile("ldmatrix.sync.aligned.m8n8.x4.shared.b16 {%0,%1,%2,%3}, [%4];"
                 : "=r"(r[0]), "=r"(r[1]), "=r"(r[2]), "=r"(r[3]) : "r"(addr));
}
__device__ __forceinline__ void ldsm4t(uint32_t r[4], uint32_t addr) {
    asm volatile("ldmatrix.sync.aligned.m8n8.x4.trans.shared.b16 {%0,%1,%2,%3}, [%4];"
                 : "=r"(r[0]), "=r"(r[1]), "=r"(r[2]), "=r"(r[3]) : "r"(addr));
}
__device__ __forceinline__ void mma16816(float c[4], const uint32_t a[4],
                                         uint32_t b0, uint32_t b1) {
    asm volatile("mma.sync.aligned.m16n8k16.row.col.f32.bf16.bf16.f32 "
                 "{%0,%1,%2,%3}, {%4,%5,%6,%7}, {%8,%9}, {%0,%1,%2,%3};"
                 : "+f"(c[0]), "+f"(c[1]), "+f"(c[2]), "+f"(c[3])
                 : "r"(a[0]), "r"(a[1]), "r"(a[2]), "r"(a[3]), "r"(b0), "r"(b1));
}
__device__ __forceinline__ uint32_t pack_bf2(float a, float b) {
    __nv_bfloat162 t = __floats2bfloat162_rn(a, b);
    return *(uint32_t*)&t;
}
__device__ __forceinline__ uint32_t pack_bf2_res(float a, float b, uint32_t hi) {
    __nv_bfloat162 h = *(__nv_bfloat162*)&hi;
    return pack_bf2(a - __bfloat162float(h.x), b - __bfloat162float(h.y));
}
__device__ __forceinline__ void split4(char* hi, char* lo, int hoff, float4 v) {
    __nv_bfloat162 h01 = __floats2bfloat162_rn(v.x, v.y);
    __nv_bfloat162 h23 = __floats2bfloat162_rn(v.z, v.w);
    __nv_bfloat162 l01 = __floats2bfloat162_rn(v.x - __bfloat162float(h01.x),
                                               v.y - __bfloat162float(h01.y));
    __nv_bfloat162 l23 = __floats2bfloat162_rn(v.z - __bfloat162float(h23.x),
                                               v.w - __bfloat162float(h23.y));
    *(uint2*)(hi + hoff * 2) = make_uint2(*(uint32_t*)&h01, *(uint32_t*)&h23);
    *(uint2*)(lo + hoff * 2) = make_uint2(*(uint32_t*)&l01, *(uint32_t*)&l23);
}
__device__ __forceinline__ void cpa16(uint32_t dst, const void* src) {
    asm volatile("cp.async.cg.shared.global [%0], [%1], 16;" :: "r"(dst), "l"(src));
}
#define CP_COMMIT asm volatile("cp.async.commit_group;" ::: "memory")
#define CP_WAIT0  asm volatile("cp.async.wait_group 0;" ::: "memory")

// ===========================================================================
// HMMA split-fp32 GEMM: C = alpha * A @ B^T + bias
// 128x128 tile, KC=32, 8 warps (4m x 2n).
// PERM_A:    A row m read from physical row (m % TV)*BV + (m / TV)
// SPLIT_OUT: write bf16 hi/lo planes (Ch, Cl) instead of fp32 C
// ===========================================================================
template <bool PERM_A, bool SPLIT_OUT>
__global__ __launch_bounds__(256, 1)
void mma_gemm(const float* __restrict__ A, int lda,
              const float* __restrict__ Bm, int ldb,
              const float* __restrict__ bias,
              float* __restrict__ C,
              __nv_bfloat16* __restrict__ Ch, __nv_bfloat16* __restrict__ Cl,
              int ldc, int K, float alpha)
{
    extern __shared__ char smem[];
    constexpr int NTILE  = 128;
    constexpr int NBW    = NTILE / 16;
    constexpr int ABYTES = 128 * ST2;
    constexpr int BBYTES = NTILE * ST2;
    constexpr int BUFB   = 2 * ABYTES + 2 * BBYTES;

    const int tid  = threadIdx.x;
    const int lane = tid & 31;
    const int wid  = tid >> 5;
    const int wm   = (wid & 3) * 32;
    const int wn   = (wid >> 2) * (NTILE / 2);

    const int bm = blockIdx.y * 128;
    const int bn = blockIdx.x * NTILE;
    const uint32_t sb0 = smem_u32(smem);

    const int c4 = (tid & 7) * 4;
    const float* aPtr[4];
#pragma unroll
    for (int it = 0; it < 4; it++) {
        int r = bm + (tid >> 3) + it * 32;
        if (PERM_A) r = (r % TV) * BV + (r / TV);
        aPtr[it] = A + (size_t)r * lda + c4;
    }
    const float* bPtr[4];
#pragma unroll
    for (int it = 0; it < 4; it++)
        bPtr[it] = Bm + (size_t)(bn + (tid >> 3) + it * 32) * ldb + c4;

    float acc[2][NBW][4];
#pragma unroll
    for (int i = 0; i < 2; i++)
#pragma unroll
        for (int j = 0; j < NBW; j++)
#pragma unroll
            for (int q = 0; q < 4; q++) acc[i][j][q] = 0.f;

    const int nc = K / KC;
    float4 pfA[4], pfB[4];

#pragma unroll
    for (int it = 0; it < 4; it++) pfA[it] = *(const float4*)(aPtr[it]);
#pragma unroll
    for (int it = 0; it < 4; it++) pfB[it] = *(const float4*)(bPtr[it]);
    {
        char* Ah = smem;            char* Al = smem + ABYTES;
        char* Bh = smem + 2*ABYTES; char* Bl = Bh + BBYTES;
#pragma unroll
        for (int it = 0; it < 4; it++)
            split4(Ah, Al, ((tid >> 3) + it * 32) * ST + c4, pfA[it]);
#pragma unroll
        for (int it = 0; it < 4; it++)
            split4(Bh, Bl, ((tid >> 3) + it * 32) * ST + c4, pfB[it]);
    }
    __syncthreads();

    for (int ci = 0; ci < nc; ci++) {
        const bool more = (ci + 1 < nc);
        if (more) {
            const int k0 = (ci + 1) * KC;
#pragma unroll
            for (int it = 0; it < 4; it++) pfA[it] = *(const float4*)(aPtr[it] + k0);
#pragma unroll
            for (int it = 0; it < 4; it++) pfB[it] = *(const float4*)(bPtr[it] + k0);
        }
        {
            const uint32_t sb  = sb0 + (ci & 1) * BUFB;
            const uint32_t sAh = sb, sAl = sb + ABYTES;
            const uint32_t sBh = sb + 2 * ABYTES, sBl = sBh + BBYTES;
            const int arow  = wm + (lane & 15);
            const int nrow0 = wn + (lane & 7) + ((lane >> 4) << 3);
            const int kbB = ((lane >> 3) & 1) * 8;
            const int kbA = (lane >> 4) * 8;
#pragma unroll
            for (int kk = 0; kk < KC; kk += 16) {
                uint32_t ah[2][4], al[2][4];
                const uint32_t aoff = arow * ST2 + (kk + kbA) * 2;
                ldsm4(ah[0], sAh + aoff);
                ldsm4(ah[1], sAh + aoff + 16 * ST2);
                ldsm4(al[0], sAl + aoff);
                ldsm4(al[1], sAl + aoff + 16 * ST2);
#pragma unroll
                for (int p = 0; p < NBW / 2; p++) {
                    uint32_t bh[4], bl[4];
                    const uint32_t boff = (nrow0 + p * 16) * ST2 + (kk + kbB) * 2;
                    ldsm4(bh, sBh + boff);
                    ldsm4(bl, sBl + boff);
#pragma unroll
                    for (int fm = 0; fm < 2; fm++) {
                        mma16816(acc[fm][2*p  ], ah[fm], bh[0], bh[1]);
                        mma16816(acc[fm][2*p  ], ah[fm], bl[0], bl[1]);
                        mma16816(acc[fm][2*p  ], al[fm], bh[0], bh[1]);
                        mma16816(acc[fm][2*p+1], ah[fm], bh[2], bh[3]);
                        mma16816(acc[fm][2*p+1], ah[fm], bl[2], bl[3]);
                        mma16816(acc[fm][2*p+1], al[fm], bh[2], bh[3]);
                    }
                }
            }
        }
        if (more) {
            char* base = smem + ((ci + 1) & 1) * BUFB;
            char* Ah = base;            char* Al = base + ABYTES;
            char* Bh = base + 2*ABYTES; char* Bl = Bh + BBYTES;
#pragma unroll
            for (int it = 0; it < 4; it++)
                split4(Ah, Al, ((tid >> 3) + it * 32) * ST + c4, pfA[it]);
#pragma unroll
            for (int it = 0; it < 4; it++)
                split4(Bh, Bl, ((tid >> 3) + it * 32) * ST + c4, pfB[it]);
        }
        __syncthreads();
    }

#pragma unroll
    for (int fm = 0; fm < 2; fm++) {
#pragma unroll
        for (int nb = 0; nb < NBW; nb++) {
            const int row = bm + wm + fm * 16 + (lane >> 2);
            const int col = bn + wn + nb * 8 + (lane & 3) * 2;
            float b0 = 0.f, b1 = 0.f;
            if (bias) { b0 = bias[col]; b1 = bias[col + 1]; }
            const float v0 = alpha * acc[fm][nb][0] + b0;
            const float v1 = alpha * acc[fm][nb][1] + b1;
            const float v2 = alpha * acc[fm][nb][2] + b0;
            const float v3 = alpha * acc[fm][nb][3] + b1;
            if (SPLIT_OUT) {
                __nv_bfloat162 h01 = __floats2bfloat162_rn(v0, v1);
                __nv_bfloat162 h23 = __floats2bfloat162_rn(v2, v3);
                __nv_bfloat162 l01 = __floats2bfloat162_rn(v0 - __bfloat162float(h01.x),
                                                           v1 - __bfloat162float(h01.y));
                __nv_bfloat162 l23 = __floats2bfloat162_rn(v2 - __bfloat162float(h23.x),
                                                           v3 - __bfloat162float(h23.y));
                *(__nv_bfloat162*)(Ch + (size_t)row * ldc + col)       = h01;
                *(__nv_bfloat162*)(Cl + (size_t)row * ldc + col)       = l01;
                *(__nv_bfloat162*)(Ch + (size_t)(row + 8) * ldc + col) = h23;
                *(__nv_bfloat162*)(Cl + (size_t)(row + 8) * ldc + col) = l23;
            } else {
                *(float2*)(C + (size_t)row * ldc + col)       = make_float2(v0, v1);
                *(float2*)(C + (size_t)(row + 8) * ldc + col) = make_float2(v2, v3);
            }
        }
    }
}

// ===========================================================================
// Fused flash attention: CTA = (64 q-rows, head h), 128 threads (4 warps,
// 16 q-rows each), 2 CTAs/SM. KV tiles of 128 staged by cp.async from the
// pre-split bf16 hi/lo planes. Online softmax; 3-term split HMMA for QK^T
// and PV. Writes g_y[s][h*64+d] (fp32).
// ===========================================================================
__global__ __launch_bounds__(128, 2)
void flash_attn(const __nv_bfloat16* __restrict__ qh_g,
                const __nv_bfloat16* __restrict__ ql_g,
                float* __restrict__ y)
{
    extern __shared__ char smem[];
    const int h  = blockIdx.y;
    const int q0 = blockIdx.x * 64;
    const int tid = threadIdx.x, lane = tid & 31, wid = tid >> 5;

    constexpr int QPB = 64 * FST2;     // 9216
    constexpr int KPB = 128 * FST2;    // 18432
    const uint32_t sQh = smem_u32(smem);
    const uint32_t sQl = sQh + QPB;
    const uint32_t sKh = sQl + QPB;
    const uint32_t sKl = sKh + KPB;
    const uint32_t sVh = sKl + KPB;
    const uint32_t sVl = sVh + KPB;

    // ---- stage Q (once): thread -> row tid>>1, 4 chunks of 16B per plane ----
    {
        const int r  = tid >> 1;
        const int cb = (tid & 1) * 4;
        const __nv_bfloat16* srcH = qh_g + (size_t)(q0 + r) * D3 + h * HD;
        const __nv_bfloat16* srcL = ql_g + (size_t)(q0 + r) * D3 + h * HD;
        const uint32_t dst = r * FST2;
#pragma unroll
        for (int c = 0; c < 4; c++) {
            cpa16(sQh + dst + (cb + c) * 16, srcH + (cb + c) * 8);
            cpa16(sQl + dst + (cb + c) * 16, srcL + (cb + c) * 8);
        }
    }
    // ---- KV staging: thread -> row tid, 8 chunks x 4 planes ----
#define STAGE_KV(j) do { \
        const size_t rowb = (size_t)((j) * 128 + tid) * D3 + h * HD; \
        const __nv_bfloat16* kh = qh_g + rowb + DV; \
        const __nv_bfloat16* kl = ql_g + rowb + DV; \
        const __nv_bfloat16* vh = qh_g + rowb + 2 * DV; \
        const __nv_bfloat16* vl = ql_g + rowb + 2 * DV; \
        const uint32_t d = tid * FST2; \
        _Pragma("unroll") \
        for (int c = 0; c < 8; c++) { \
            cpa16(sKh + d + c * 16, kh + c * 8); \
            cpa16(sKl + d + c * 16, kl + c * 8); \
            cpa16(sVh + d + c * 16, vh + c * 8); \
            cpa16(sVl + d + c * 16, vl + c * 8); \
        } \
    } while (0)

    STAGE_KV(0);
    CP_COMMIT; CP_WAIT0;
    __syncthreads();

    // ---- preload Q fragments (16 rows x 64 k per warp) ----
    uint32_t qfh[4][4], qfl[4][4];
    {
        const int arow = wid * 16 + (lane & 15);
        const int kbA  = (lane >> 4) * 8;
#pragma unroll
        for (int ks = 0; ks < 4; ks++) {
            const uint32_t off = arow * FST2 + (ks * 16 + kbA) * 2;
            ldsm4(qfh[ks], sQh + off);
            ldsm4(qfl[ks], sQl + off);
        }
    }

    float accY[8][4];
#pragma unroll
    for (int i = 0; i < 8; i++)
#pragma unroll
        for (int j = 0; j < 4; j++) accY[i][j] = 0.f;
    float m0 = -1e30f, m1 = -1e30f, l0 = 0.f, l1 = 0.f;

    const float cs = 0.125f * 1.4426950408889634f;   // 1/8 * log2(e)
    const int nrow = (lane & 7) + ((lane >> 4) << 3);
    const int kbB  = ((lane >> 3) & 1) * 8;
    const int trow = (lane & 15);
    const int dbas = ((lane >> 4) << 3);

    for (int kv = 0; kv < SS / 128; kv++) {
        // ---- S = Q K^T (warp: 16 x 128), 3-term split ----
        float accS[16][4];
#pragma unroll
        for (int i = 0; i < 16; i++)
#pragma unroll
            for (int j = 0; j < 4; j++) accS[i][j] = 0.f;
#pragma unroll
        for (int ks = 0; ks < 4; ks++) {
#pragma unroll
            for (int g = 0; g < 8; g++) {
                uint32_t bh[4], bl[4];
                const uint32_t boff = (g * 16 + nrow) * FST2 + (ks * 16 + kbB) * 2;
                ldsm4(bh, sKh + boff);
                ldsm4(bl, sKl + boff);
                mma16816(accS[2*g  ], qfh[ks], bh[0], bh[1]);
                mma16816(accS[2*g  ], qfh[ks], bl[0], bl[1]);
                mma16816(accS[2*g  ], qfl[ks], bh[0], bh[1]);
                mma16816(accS[2*g+1], qfh[ks], bh[2], bh[3]);
                mma16816(accS[2*g+1], qfh[ks], bl[2], bl[3]);
                mma16816(accS[2*g+1], qfl[ks], bh[2], bh[3]);
            }
        }

        // ---- online softmax (rows lane>>2 and +8) ----
        float mc0 = -1e30f, mc1 = -1e30f;
#pragma unroll
        for (int nb = 0; nb < 16; nb++) {
            accS[nb][0] *= cs; accS[nb][1] *= cs;
            accS[nb][2] *= cs; accS[nb][3] *= cs;
            mc0 = fmaxf(mc0, fmaxf(accS[nb][0], accS[nb][1]));
            mc1 = fmaxf(mc1, fmaxf(accS[nb][2], accS[nb][3]));
        }
        mc0 = fmaxf(mc0, __shfl_xor_sync(~0u, mc0, 1));
        mc0 = fmaxf(mc0, __shfl_xor_sync(~0u, mc0, 2));
        mc1 = fmaxf(mc1, __shfl_xor_sync(~0u, mc1, 1));
        mc1 = fmaxf(mc1, __shfl_xor_sync(~0u, mc1, 2));
        const float mn0 = fmaxf(m0, mc0), mn1 = fmaxf(m1, mc1);
        const float f0 = exp2f(m0 - mn0), f1 = exp2f(m1 - mn1);
        m0 = mn0; m1 = mn1;

        float s0 = 0.f, s1 = 0.f;
#pragma unroll
        for (int nb = 0; nb < 16; nb++) {
            accS[nb][0] = exp2f(accS[nb][0] - mn0);
            accS[nb][1] = exp2f(accS[nb][1] - mn0);
            accS[nb][2] = exp2f(accS[nb][2] - mn1);
            accS[nb][3] = exp2f(accS[nb][3] - mn1);
            s0 += accS[nb][0] + accS[nb][1];
            s1 += accS[nb][2] + accS[nb][3];
        }
        s0 += __shfl_xor_sync(~0u, s0, 1); s0 += __shfl_xor_sync(~0u, s0, 2);
        s1 += __shfl_xor_sync(~0u, s1, 1); s1 += __shfl_xor_sync(~0u, s1, 2);
        l0 = l0 * f0 + s0;
        l1 = l1 * f1 + s1;
#pragma unroll
        for (int db = 0; db < 8; db++) {
            accY[db][0] *= f0; accY[db][1] *= f0;
            accY[db][2] *= f1; accY[db][3] *= f1;
        }

        // ---- PV: accY += P V (P from accS fragments; 3-term split) ----
#pragma unroll
        for (int ks = 0; ks < 8; ks++) {
            uint32_t ph[4], pl[4];
            ph[0] = pack_bf2(accS[2*ks  ][0], accS[2*ks  ][1]);
            ph[1] = pack_bf2(accS[2*ks  ][2], accS[2*ks  ][3]);
            ph[2] = pack_bf2(accS[2*ks+1][0], accS[2*ks+1][1]);
            ph[3] = pack_bf2(accS[2*ks+1][2], accS[2*ks+1][3]);
            pl[0] = pack_bf2_res(accS[2*ks  ][0], accS[2*ks  ][1], ph[0]);
            pl[1] = pack_bf2_res(accS[2*ks  ][2], accS[2*ks  ][3], ph[1]);
            pl[2] = pack_bf2_res(accS[2*ks+1][0], accS[2*ks+1][1], ph[2]);
            pl[3] = pack_bf2_res(accS[2*ks+1][2], accS[2*ks+1][3], ph[3]);
            const int tr = ks * 16 + trow;
#pragma unroll
            for (int g = 0; g < 4; g++) {
                uint32_t vh[4], vl[4];
                const uint32_t voff = tr * FST2 + (g * 16 + dbas) * 2;
                ldsm4t(vh, sVh + voff);
                ldsm4t(vl, sVl + voff);
                mma16816(accY[2*g  ], ph, vh[0], vh[1]);
                mma16816(accY[2*g  ], ph, vl[0], vl[1]);
                mma16816(accY[2*g  ], pl, vh[0], vh[1]);
                mma16816(accY[2*g+1], ph, vh[2], vh[3]);
                mma16816(accY[2*g+1], ph, vl[2], vl[3]);
                mma16816(accY[2*g+1], pl, vh[2], vh[3]);
            }
        }

        // ---- refill KV buffer for next tile ----
        __syncthreads();                 // all warps done reading this tile
        if (kv + 1 < SS / 128) {
            STAGE_KV(kv + 1);
            CP_COMMIT; CP_WAIT0;
        }
        __syncthreads();                 // staged data visible to all warps
    }

    // ---- normalize + store ----
    const float il0 = 1.0f / l0, il1 = 1.0f / l1;
    const int row = q0 + wid * 16 + (lane >> 2);
#pragma unroll
    for (int db = 0; db < 8; db++) {
        const int col = h * HD + db * 8 + (lane & 3) * 2;
        *(float2*)(y + (size_t)row * DV + col) =
            make_float2(accY[db][0] * il0, accY[db][1] * il0);
        *(float2*)(y + (size_t)(row + 8) * DV + col) =
            make_float2(accY[db][2] * il1, accY[db][3] * il1);
    }
#undef STAGE_KV
}

// ---------------------------------------------------------------------------
extern "C" void kernel_launch(void* const* d_in, const int* in_sizes, int n_in,
                              void* d_out, int out_size)
{
    const float* x    = (const float*)d_in[0];
    const float* Wqkv = (const float*)d_in[1];
    const float* bqkv = (const float*)d_in[2];
    const float* Wout = (const float*)d_in[3];
    const float* bout = (const float*)d_in[4];
    float* out = (float*)d_out;

    __nv_bfloat16* qh; cudaGetSymbolAddress((void**)&qh, g_qkv_h);
    __nv_bfloat16* ql; cudaGetSymbolAddress((void**)&ql, g_qkv_l);
    float* y;          cudaGetSymbolAddress((void**)&y,  g_y);

    constexpr int SMEM_G = 2 * (2 * 128 * ST2 + 2 * 128 * ST2);        // 81920
    constexpr int SMEM_F = 2 * 64 * FST2 + 4 * 128 * FST2;             // 92160

    cudaFuncSetAttribute(mma_gemm<false, true>,
                         cudaFuncAttributeMaxDynamicSharedMemorySize, SMEM_G);
    cudaFuncSetAttribute(mma_gemm<true, false>,
                         cudaFuncAttributeMaxDynamicSharedMemorySize, SMEM_G);
    cudaFuncSetAttribute(flash_attn,
                         cudaFuncAttributeMaxDynamicSharedMemorySize, SMEM_F);

    // 1) qkv = x @ Wqkv^T + bqkv  -> bf16 hi/lo planes [S, 3D]
    mma_gemm<false, true><<<dim3(D3 / 128, SS / 128), 256, SMEM_G>>>(
        x, DV, Wqkv, DV, bqkv, nullptr, qh, ql, D3, DV, 1.0f);

    // 2) fused attention -> y[s][h*64+d]  (fp32)
    flash_attn<<<dim3(SS / 64, HH), 128, SMEM_F>>>(qh, ql, y);

    // 3) out[b*T+t] = y[t*B+b] @ Wout^T + bout  (permute folded into A reads)
    mma_gemm<true, false><<<dim3(DV / 128, SS / 128), 256, SMEM_G>>>(
        y, DV, Wout, DV, bout, out, nullptr, nullptr, DV, DV, 1.0f);
}

// round 6
// speedup vs baseline: 1.2417x; 1.2417x over previous
#include <cuda_runtime.h>
#include <cuda_bf16.h>
#include <stdint.h>

// Problem constants
#define BV 2
#define TV 1536
#define DV 1024
#define HH 16
#define HD 64
#define SS 3072            // B*T
#define D3 3072            // 3*D

// Scratch (device globals: allocation-free per harness rules)
__device__ __nv_bfloat16 g_qkv_h[(size_t)SS * D3];  // 18.9 MB hi plane
__device__ __nv_bfloat16 g_qkv_l[(size_t)SS * D3];  // 18.9 MB lo plane
__device__ float g_y[(size_t)SS * DV];              // 12.6 MB

#define KC  32             // gemm k-chunk (bf16 elems)
#define ST  40             // gemm smem row stride in halves
#define ST2 80             // ... bytes
#define FST  72            // flash smem row stride in halves (64 + 8 pad)
#define FST2 144           // ... bytes

// ---------------------------------------------------------------------------
__device__ __forceinline__ uint32_t smem_u32(const void* p) {
    uint32_t a;
    asm("{ .reg .u64 t; cvta.to.shared.u64 t, %1; cvt.u32.u64 %0, t; }"
        : "=r"(a) : "l"(p));
    return a;
}
__device__ __forceinline__ void ldsm4(uint32_t r[4], uint32_t addr) {
    asm volatile("ldmatrix.sync.aligned.m8n8.x4.shared.b16 {%0,%1,%2,%3}, [%4];"
                 : "=r"(r[0]), "=r"(r[1]), "=r"(r[2]), "=r"(r[3]) : "r"(addr));
}
__device__ __forceinline__ void ldsm4t(uint32_t r[4], uint32_t addr) {
    asm volatile("ldmatrix.sync.aligned.m8n8.x4.trans.shared.b16 {%0,%1,%2,%3}, [%4];"
                 : "=r"(r[0]), "=r"(r[1]), "=r"(r[2]), "=r"(r[3]) : "r"(addr));
}
__device__ __forceinline__ void mma16816(float c[4], const uint32_t a[4],
                                         uint32_t b0, uint32_t b1) {
    asm volatile("mma.sync.aligned.m16n8k16.row.col.f32.bf16.bf16.f32 "
                 "{%0,%1,%2,%3}, {%4,%5,%6,%7}, {%8,%9}, {%0,%1,%2,%3};"
                 : "+f"(c[0]), "+f"(c[1]), "+f"(c[2]), "+f"(c[3])
                 : "r"(a[0]), "r"(a[1]), "r"(a[2]), "r"(a[3]), "r"(b0), "r"(b1));
}
__device__ __forceinline__ uint32_t pack_bf2(float a, float b) {
    __nv_bfloat162 t = __floats2bfloat162_rn(a, b);
    return *(uint32_t*)&t;
}
__device__ __forceinline__ uint32_t pack_bf2_res(float a, float b, uint32_t hi) {
    __nv_bfloat162 h = *(__nv_bfloat162*)&hi;
    return pack_bf2(a - __bfloat162float(h.x), b - __bfloat162float(h.y));
}
__device__ __forceinline__ void split4(char* hi, char* lo, int hoff, float4 v) {
    __nv_bfloat162 h01 = __floats2bfloat162_rn(v.x, v.y);
    __nv_bfloat162 h23 = __floats2bfloat162_rn(v.z, v.w);
    __nv_bfloat162 l01 = __floats2bfloat162_rn(v.x - __bfloat162float(h01.x),
                                               v.y - __bfloat162float(h01.y));
    __nv_bfloat162 l23 = __floats2bfloat162_rn(v.z - __bfloat162float(h23.x),
                                               v.w - __bfloat162float(h23.y));
    *(uint2*)(hi + hoff * 2) = make_uint2(*(uint32_t*)&h01, *(uint32_t*)&h23);
    *(uint2*)(lo + hoff * 2) = make_uint2(*(uint32_t*)&l01, *(uint32_t*)&l23);
}
__device__ __forceinline__ void cpa16(uint32_t dst, const void* src) {
    asm volatile("cp.async.cg.shared.global [%0], [%1], 16;" :: "r"(dst), "l"(src));
}
#define CP_COMMIT asm volatile("cp.async.commit_group;" ::: "memory")
#define CP_WAIT0  asm volatile("cp.async.wait_group 0;" ::: "memory")

// ===========================================================================
// HMMA split-fp32 GEMM: C = alpha * A @ B^T + bias
// 128x128 tile, KC=32, 8 warps (4m x 2n).
// PERM_A:    A row m read from physical row (m % TV)*BV + (m / TV)
// SPLIT_OUT: write bf16 hi/lo planes (Ch, Cl) instead of fp32 C
// ===========================================================================
template <bool PERM_A, bool SPLIT_OUT>
__global__ __launch_bounds__(256, 1)
void mma_gemm(const float* __restrict__ A, int lda,
              const float* __restrict__ Bm, int ldb,
              const float* __restrict__ bias,
              float* __restrict__ C,
              __nv_bfloat16* __restrict__ Ch, __nv_bfloat16* __restrict__ Cl,
              int ldc, int K, float alpha)
{
    extern __shared__ char smem[];
    constexpr int NTILE  = 128;
    constexpr int NBW    = NTILE / 16;
    constexpr int ABYTES = 128 * ST2;
    constexpr int BBYTES = NTILE * ST2;
    constexpr int BUFB   = 2 * ABYTES + 2 * BBYTES;

    const int tid  = threadIdx.x;
    const int lane = tid & 31;
    const int wid  = tid >> 5;
    const int wm   = (wid & 3) * 32;
    const int wn   = (wid >> 2) * (NTILE / 2);

    const int bm = blockIdx.y * 128;
    const int bn = blockIdx.x * NTILE;
    const uint32_t sb0 = smem_u32(smem);

    const int c4 = (tid & 7) * 4;
    const float* aPtr[4];
#pragma unroll
    for (int it = 0; it < 4; it++) {
        int r = bm + (tid >> 3) + it * 32;
        if (PERM_A) r = (r % TV) * BV + (r / TV);
        aPtr[it] = A + (size_t)r * lda + c4;
    }
    const float* bPtr[4];
#pragma unroll
    for (int it = 0; it < 4; it++)
        bPtr[it] = Bm + (size_t)(bn + (tid >> 3) + it * 32) * ldb + c4;

    float acc[2][NBW][4];
#pragma unroll
    for (int i = 0; i < 2; i++)
#pragma unroll
        for (int j = 0; j < NBW; j++)
#pragma unroll
            for (int q = 0; q < 4; q++) acc[i][j][q] = 0.f;

    const int nc = K / KC;
    float4 pfA[4], pfB[4];

#pragma unroll
    for (int it = 0; it < 4; it++) pfA[it] = *(const float4*)(aPtr[it]);
#pragma unroll
    for (int it = 0; it < 4; it++) pfB[it] = *(const float4*)(bPtr[it]);
    {
        char* Ah = smem;            char* Al = smem + ABYTES;
        char* Bh = smem + 2*ABYTES; char* Bl = Bh + BBYTES;
#pragma unroll
        for (int it = 0; it < 4; it++)
            split4(Ah, Al, ((tid >> 3) + it * 32) * ST + c4, pfA[it]);
#pragma unroll
        for (int it = 0; it < 4; it++)
            split4(Bh, Bl, ((tid >> 3) + it * 32) * ST + c4, pfB[it]);
    }
    __syncthreads();

    for (int ci = 0; ci < nc; ci++) {
        const bool more = (ci + 1 < nc);
        if (more) {
            const int k0 = (ci + 1) * KC;
#pragma unroll
            for (int it = 0; it < 4; it++) pfA[it] = *(const float4*)(aPtr[it] + k0);
#pragma unroll
            for (int it = 0; it < 4; it++) pfB[it] = *(const float4*)(bPtr[it] + k0);
        }
        {
            const uint32_t sb  = sb0 + (ci & 1) * BUFB;
            const uint32_t sAh = sb, sAl = sb + ABYTES;
            const uint32_t sBh = sb + 2 * ABYTES, sBl = sBh + BBYTES;
            const int arow  = wm + (lane & 15);
            const int nrow0 = wn + (lane & 7) + ((lane >> 4) << 3);
            const int kbB = ((lane >> 3) & 1) * 8;
            const int kbA = (lane >> 4) * 8;
#pragma unroll
            for (int kk = 0; kk < KC; kk += 16) {
                uint32_t ah[2][4], al[2][4];
                const uint32_t aoff = arow * ST2 + (kk + kbA) * 2;
                ldsm4(ah[0], sAh + aoff);
                ldsm4(ah[1], sAh + aoff + 16 * ST2);
                ldsm4(al[0], sAl + aoff);
                ldsm4(al[1], sAl + aoff + 16 * ST2);
#pragma unroll
                for (int p = 0; p < NBW / 2; p++) {
                    uint32_t bh[4], bl[4];
                    const uint32_t boff = (nrow0 + p * 16) * ST2 + (kk + kbB) * 2;
                    ldsm4(bh, sBh + boff);
                    ldsm4(bl, sBl + boff);
#pragma unroll
                    for (int fm = 0; fm < 2; fm++) {
                        mma16816(acc[fm][2*p  ], ah[fm], bh[0], bh[1]);
                        mma16816(acc[fm][2*p  ], ah[fm], bl[0], bl[1]);
                        mma16816(acc[fm][2*p  ], al[fm], bh[0], bh[1]);
                        mma16816(acc[fm][2*p+1], ah[fm], bh[2], bh[3]);
                        mma16816(acc[fm][2*p+1], ah[fm], bl[2], bl[3]);
                        mma16816(acc[fm][2*p+1], al[fm], bh[2], bh[3]);
                    }
                }
            }
        }
        if (more) {
            char* base = smem + ((ci + 1) & 1) * BUFB;
            char* Ah = base;            char* Al = base + ABYTES;
            char* Bh = base + 2*ABYTES; char* Bl = Bh + BBYTES;
#pragma unroll
            for (int it = 0; it < 4; it++)
                split4(Ah, Al, ((tid >> 3) + it * 32) * ST + c4, pfA[it]);
#pragma unroll
            for (int it = 0; it < 4; it++)
                split4(Bh, Bl, ((tid >> 3) + it * 32) * ST + c4, pfB[it]);
        }
        __syncthreads();
    }

#pragma unroll
    for (int fm = 0; fm < 2; fm++) {
#pragma unroll
        for (int nb = 0; nb < NBW; nb++) {
            const int row = bm + wm + fm * 16 + (lane >> 2);
            const int col = bn + wn + nb * 8 + (lane & 3) * 2;
            float b0 = 0.f, b1 = 0.f;
            if (bias) { b0 = bias[col]; b1 = bias[col + 1]; }
            const float v0 = alpha * acc[fm][nb][0] + b0;
            const float v1 = alpha * acc[fm][nb][1] + b1;
            const float v2 = alpha * acc[fm][nb][2] + b0;
            const float v3 = alpha * acc[fm][nb][3] + b1;
            if (SPLIT_OUT) {
                __nv_bfloat162 h01 = __floats2bfloat162_rn(v0, v1);
                __nv_bfloat162 h23 = __floats2bfloat162_rn(v2, v3);
                __nv_bfloat162 l01 = __floats2bfloat162_rn(v0 - __bfloat162float(h01.x),
                                                           v1 - __bfloat162float(h01.y));
                __nv_bfloat162 l23 = __floats2bfloat162_rn(v2 - __bfloat162float(h23.x),
                                                           v3 - __bfloat162float(h23.y));
                *(__nv_bfloat162*)(Ch + (size_t)row * ldc + col)       = h01;
                *(__nv_bfloat162*)(Cl + (size_t)row * ldc + col)       = l01;
                *(__nv_bfloat162*)(Ch + (size_t)(row + 8) * ldc + col) = h23;
                *(__nv_bfloat162*)(Cl + (size_t)(row + 8) * ldc + col) = l23;
            } else {
                *(float2*)(C + (size_t)row * ldc + col)       = make_float2(v0, v1);
                *(float2*)(C + (size_t)(row + 8) * ldc + col) = make_float2(v2, v3);
            }
        }
    }
}

// ===========================================================================
// Fused flash attention: CTA = (128 q-rows, head h), 256 threads (8 warps,
// 16 q-rows each), 1 CTA/SM. KV tiles of 128 staged via cp.async from the
// pre-split bf16 hi/lo planes into DOUBLE-BUFFERED smem; the prefetch of
// tile kv+1 is issued before computing tile kv. One barrier per iteration.
// ===========================================================================
__global__ __launch_bounds__(256, 1)
void flash_attn(const __nv_bfloat16* __restrict__ qh_g,
                const __nv_bfloat16* __restrict__ ql_g,
                float* __restrict__ y)
{
    extern __shared__ char smem[];
    const int h  = blockIdx.y;
    const int q0 = blockIdx.x * 128;
    const int tid = threadIdx.x, lane = tid & 31, wid = tid >> 5;

    constexpr int QPB = 128 * FST2;    // 18432 per plane
    constexpr int KVB = 4 * QPB;       // Kh,Kl,Vh,Vl per buffer = 73728
    const uint32_t sQh = smem_u32(smem);
    const uint32_t sQl = sQh + QPB;
    const uint32_t sKV = sQl + QPB;    // two KV buffers follow

    // ---- stage Q once: thread -> row tid>>1, 4 chunks of 16B per plane ----
    {
        const int r  = tid >> 1;
        const int cb = (tid & 1) * 4;
        const __nv_bfloat16* srcH = qh_g + (size_t)(q0 + r) * D3 + h * HD;
        const __nv_bfloat16* srcL = ql_g + (size_t)(q0 + r) * D3 + h * HD;
        const uint32_t dst = r * FST2;
#pragma unroll
        for (int c = 0; c < 4; c++) {
            cpa16(sQh + dst + (cb + c) * 16, srcH + (cb + c) * 8);
            cpa16(sQl + dst + (cb + c) * 16, srcL + (cb + c) * 8);
        }
    }
    // ---- KV staging into buffer b: thread -> row tid>>1, 4 chunks/plane ----
#define STAGE_KV(j, b) do { \
        const int r_  = tid >> 1; \
        const int cb_ = (tid & 1) * 4; \
        const size_t rowb = (size_t)((j) * 128 + r_) * D3 + h * HD; \
        const uint32_t base = sKV + (b) * KVB; \
        const uint32_t d = r_ * FST2; \
        _Pragma("unroll") \
        for (int c = 0; c < 4; c++) { \
            const int cc = cb_ + c; \
            cpa16(base + 0 * QPB + d + cc * 16, qh_g + rowb + DV + cc * 8); \
            cpa16(base + 1 * QPB + d + cc * 16, ql_g + rowb + DV + cc * 8); \
            cpa16(base + 2 * QPB + d + cc * 16, qh_g + rowb + 2 * DV + cc * 8); \
            cpa16(base + 3 * QPB + d + cc * 16, ql_g + rowb + 2 * DV + cc * 8); \
        } \
    } while (0)

    STAGE_KV(0, 0);
    CP_COMMIT; CP_WAIT0;
    __syncthreads();

    // ---- preload Q fragments (16 rows x 64 k per warp) ----
    uint32_t qfh[4][4], qfl[4][4];
    {
        const int arow = wid * 16 + (lane & 15);
        const int kbA  = (lane >> 4) * 8;
#pragma unroll
        for (int ks = 0; ks < 4; ks++) {
            const uint32_t off = arow * FST2 + (ks * 16 + kbA) * 2;
            ldsm4(qfh[ks], sQh + off);
            ldsm4(qfl[ks], sQl + off);
        }
    }

    float accY[8][4];
#pragma unroll
    for (int i = 0; i < 8; i++)
#pragma unroll
        for (int j = 0; j < 4; j++) accY[i][j] = 0.f;
    float m0 = -1e30f, m1 = -1e30f, l0 = 0.f, l1 = 0.f;

    const float cs = 0.125f * 1.4426950408889634f;   // 1/8 * log2(e)
    const int nrow = (lane & 7) + ((lane >> 4) << 3);
    const int kbB  = ((lane >> 3) & 1) * 8;
    const int trow = (lane & 15);
    const int dbas = ((lane >> 4) << 3);

    constexpr int NT = SS / 128;
    for (int kv = 0; kv < NT; kv++) {
        // prefetch next KV tile into the other buffer (overlaps with compute)
        const bool more = (kv + 1 < NT);
        if (more) { STAGE_KV(kv + 1, (kv + 1) & 1); CP_COMMIT; }

        const uint32_t bb  = sKV + (kv & 1) * KVB;
        const uint32_t sKh = bb, sKl = bb + QPB, sVh = bb + 2*QPB, sVl = bb + 3*QPB;

        // ---- S = Q K^T (warp: 16 x 128), 3-term split ----
        float accS[16][4];
#pragma unroll
        for (int i = 0; i < 16; i++)
#pragma unroll
            for (int j = 0; j < 4; j++) accS[i][j] = 0.f;
#pragma unroll
        for (int ks = 0; ks < 4; ks++) {
#pragma unroll
            for (int g = 0; g < 8; g++) {
                uint32_t bh[4], bl[4];
                const uint32_t boff = (g * 16 + nrow) * FST2 + (ks * 16 + kbB) * 2;
                ldsm4(bh, sKh + boff);
                ldsm4(bl, sKl + boff);
                mma16816(accS[2*g  ], qfh[ks], bh[0], bh[1]);
                mma16816(accS[2*g  ], qfh[ks], bl[0], bl[1]);
                mma16816(accS[2*g  ], qfl[ks], bh[0], bh[1]);
                mma16816(accS[2*g+1], qfh[ks], bh[2], bh[3]);
                mma16816(accS[2*g+1], qfh[ks], bl[2], bl[3]);
                mma16816(accS[2*g+1], qfl[ks], bh[2], bh[3]);
            }
        }

        // ---- online softmax (rows lane>>2 and +8) ----
        float mc0 = -1e30f, mc1 = -1e30f;
#pragma unroll
        for (int nb = 0; nb < 16; nb++) {
            accS[nb][0] *= cs; accS[nb][1] *= cs;
            accS[nb][2] *= cs; accS[nb][3] *= cs;
            mc0 = fmaxf(mc0, fmaxf(accS[nb][0], accS[nb][1]));
            mc1 = fmaxf(mc1, fmaxf(accS[nb][2], accS[nb][3]));
        }
        mc0 = fmaxf(mc0, __shfl_xor_sync(~0u, mc0, 1));
        mc0 = fmaxf(mc0, __shfl_xor_sync(~0u, mc0, 2));
        mc1 = fmaxf(mc1, __shfl_xor_sync(~0u, mc1, 1));
        mc1 = fmaxf(mc1, __shfl_xor_sync(~0u, mc1, 2));
        const float mn0 = fmaxf(m0, mc0), mn1 = fmaxf(m1, mc1);
        const float f0 = exp2f(m0 - mn0), f1 = exp2f(m1 - mn1);
        m0 = mn0; m1 = mn1;

        float s0 = 0.f, s1 = 0.f;
#pragma unroll
        for (int nb = 0; nb < 16; nb++) {
            accS[nb][0] = exp2f(accS[nb][0] - mn0);
            accS[nb][1] = exp2f(accS[nb][1] - mn0);
            accS[nb][2] = exp2f(accS[nb][2] - mn1);
            accS[nb][3] = exp2f(accS[nb][3] - mn1);
            s0 += accS[nb][0] + accS[nb][1];
            s1 += accS[nb][2] + accS[nb][3];
        }
        s0 += __shfl_xor_sync(~0u, s0, 1); s0 += __shfl_xor_sync(~0u, s0, 2);
        s1 += __shfl_xor_sync(~0u, s1, 1); s1 += __shfl_xor_sync(~0u, s1, 2);
        l0 = l0 * f0 + s0;
        l1 = l1 * f1 + s1;
#pragma unroll
        for (int db = 0; db < 8; db++) {
            accY[db][0] *= f0; accY[db][1] *= f0;
            accY[db][2] *= f1; accY[db][3] *= f1;
        }

        // ---- PV: accY += P V (P from accS fragments; 3-term split) ----
#pragma unroll
        for (int ks = 0; ks < 8; ks++) {
            uint32_t ph[4], pl[4];
            ph[0] = pack_bf2(accS[2*ks  ][0], accS[2*ks  ][1]);
            ph[1] = pack_bf2(accS[2*ks  ][2], accS[2*ks  ][3]);
            ph[2] = pack_bf2(accS[2*ks+1][0], accS[2*ks+1][1]);
            ph[3] = pack_bf2(accS[2*ks+1][2], accS[2*ks+1][3]);
            pl[0] = pack_bf2_res(accS[2*ks  ][0], accS[2*ks  ][1], ph[0]);
            pl[1] = pack_bf2_res(accS[2*ks  ][2], accS[2*ks  ][3], ph[1]);
            pl[2] = pack_bf2_res(accS[2*ks+1][0], accS[2*ks+1][1], ph[2]);
            pl[3] = pack_bf2_res(accS[2*ks+1][2], accS[2*ks+1][3], ph[3]);
            const int tr = ks * 16 + trow;
#pragma unroll
            for (int g = 0; g < 4; g++) {
                uint32_t vh[4], vl[4];
                const uint32_t voff = tr * FST2 + (g * 16 + dbas) * 2;
                ldsm4t(vh, sVh + voff);
                ldsm4t(vl, sVl + voff);
                mma16816(accY[2*g  ], ph, vh[0], vh[1]);
                mma16816(accY[2*g  ], ph, vl[0], vl[1]);
                mma16816(accY[2*g  ], pl, vh[0], vh[1]);
                mma16816(accY[2*g+1], ph, vh[2], vh[3]);
                mma16816(accY[2*g+1], ph, vl[2], vl[3]);
                mma16816(accY[2*g+1], pl, vh[2], vh[3]);
            }
        }

        if (more) {
            CP_WAIT0;          // prefetched tile kv+1 has landed
            __syncthreads();   // ... and everyone is done reading buffer kv&1
        }
    }

    // ---- normalize + store ----
    const float il0 = 1.0f / l0, il1 = 1.0f / l1;
    const int row = q0 + wid * 16 + (lane >> 2);
#pragma unroll
    for (int db = 0; db < 8; db++) {
        const int col = h * HD + db * 8 + (lane & 3) * 2;
        *(float2*)(y + (size_t)row * DV + col) =
            make_float2(accY[db][0] * il0, accY[db][1] * il0);
        *(float2*)(y + (size_t)(row + 8) * DV + col) =
            make_float2(accY[db][2] * il1, accY[db][3] * il1);
    }
#undef STAGE_KV
}

// ---------------------------------------------------------------------------
extern "C" void kernel_launch(void* const* d_in, const int* in_sizes, int n_in,
                              void* d_out, int out_size)
{
    const float* x    = (const float*)d_in[0];
    const float* Wqkv = (const float*)d_in[1];
    const float* bqkv = (const float*)d_in[2];
    const float* Wout = (const float*)d_in[3];
    const float* bout = (const float*)d_in[4];
    float* out = (float*)d_out;

    __nv_bfloat16* qh; cudaGetSymbolAddress((void**)&qh, g_qkv_h);
    __nv_bfloat16* ql; cudaGetSymbolAddress((void**)&ql, g_qkv_l);
    float* y;          cudaGetSymbolAddress((void**)&y,  g_y);

    constexpr int SMEM_G = 2 * (2 * 128 * ST2 + 2 * 128 * ST2);        // 81920
    constexpr int SMEM_F = 2 * 128 * FST2 + 2 * 4 * 128 * FST2;        // 184320

    cudaFuncSetAttribute(mma_gemm<false, true>,
                         cudaFuncAttributeMaxDynamicSharedMemorySize, SMEM_G);
    cudaFuncSetAttribute(mma_gemm<true, false>,
                         cudaFuncAttributeMaxDynamicSharedMemorySize, SMEM_G);
    cudaFuncSetAttribute(flash_attn,
                         cudaFuncAttributeMaxDynamicSharedMemorySize, SMEM_F);

    // 1) qkv = x @ Wqkv^T + bqkv  -> bf16 hi/lo planes [S, 3D]
    mma_gemm<false, true><<<dim3(D3 / 128, SS / 128), 256, SMEM_G>>>(
        x, DV, Wqkv, DV, bqkv, nullptr, qh, ql, D3, DV, 1.0f);

    // 2) fused attention -> y[s][h*64+d]  (fp32)
    flash_attn<<<dim3(SS / 128, HH), 256, SMEM_F>>>(qh, ql, y);

    // 3) out[b*T+t] = y[t*B+b] @ Wout^T + bout  (permute folded into A reads)
    mma_gemm<true, false><<<dim3(DV / 128, SS / 128), 256, SMEM_G>>>(
        y, DV, Wout, DV, bout, out, nullptr, nullptr, DV, DV, 1.0f);
}